// round 4
// baseline (speedup 1.0000x reference)
#include <cuda_runtime.h>
#include <cuda_bf16.h>
#include <stdint.h>

#define B_ 128
#define T_ 256
#define H_ 512
#define G4 2048          // 4*H, gate-interleaved columns p = 4*jh + gate
#define KU 1024          // unique split-K: [hi(512) | lo(512)]
#define M_ (B_*T_)       // 32768

// ---------------- device scratch (no allocs allowed) ----------------
__device__ __nv_bfloat16 g_wsplit[4][G4][KU];   // W1,U1,W2,U2: [n=p][ hi(0..511) | lo(512..1023) ]
__device__ float         g_bias[2][G4];
__device__ __nv_bfloat16 g_xsplit[M_][KU];      // activations split (input of big GEMM)
__device__ float         g_Zx[M_][G4];          // x@W + b (gate-interleaved cols), 256MB
__device__ __nv_bfloat16 g_hsplit[2][B_][KU];   // double-buffered split h
__device__ float         g_c[B_][H_];
__device__ unsigned      g_flags[128];          // grid barrier flags (monotonic)

// ---------------- helpers ----------------
#define MMA16816(d, a, b) asm volatile( \
  "mma.sync.aligned.m16n8k16.row.col.f32.bf16.bf16.f32 " \
  "{%0,%1,%2,%3}, {%4,%5,%6,%7}, {%8,%9}, {%0,%1,%2,%3};\n" \
  : "+f"(d[0]), "+f"(d[1]), "+f"(d[2]), "+f"(d[3]) \
  : "r"(a[0]), "r"(a[1]), "r"(a[2]), "r"(a[3]), "r"(b[0]), "r"(b[1]))

__device__ __forceinline__ void cpa16(void* s, const void* g) {
  uint32_t sa = (uint32_t)__cvta_generic_to_shared(s);
  asm volatile("cp.async.cg.shared.global [%0], [%1], 16;\n" :: "r"(sa), "l"(g));
}
#define CP_COMMIT asm volatile("cp.async.commit_group;\n")
#define CP_WAIT0  asm volatile("cp.async.wait_group 0;\n")

template<int RS>
__device__ __forceinline__ void ldA(uint32_t a[4], const __nv_bfloat16* t, int grp, int qid) {
  const __nv_bfloat16* p = t + grp*RS + qid*2;
  a[0] = *(const uint32_t*)p;
  a[1] = *(const uint32_t*)(p + 8*RS);
  a[2] = *(const uint32_t*)(p + 8);
  a[3] = *(const uint32_t*)(p + 8*RS + 8);
}
template<int RS>
__device__ __forceinline__ void ldBf(uint32_t b[2], const __nv_bfloat16* t, int grp, int qid) {
  const __nv_bfloat16* p = t + grp*RS + qid*2;
  b[0] = *(const uint32_t*)p;
  b[1] = *(const uint32_t*)(p + 8);
}

__device__ __forceinline__ float sigf(float x)     { return 1.f / (1.f + __expf(-x)); }
__device__ __forceinline__ float tanhfast(float x) { return 1.f - 2.f / (1.f + __expf(2.f*x)); }

// Grid barrier across 128 CTAs (blockDim.x == 128). Monotonic targets; replay-safe.
__device__ __forceinline__ void grid_barrier(unsigned target, int ctaId) {
  __threadfence();
  __syncthreads();
  if (threadIdx.x == 0)
    asm volatile("st.release.gpu.global.u32 [%0], %1;\n"
                 :: "l"(&g_flags[ctaId]), "r"(target) : "memory");
  unsigned v;
  do {
    asm volatile("ld.acquire.gpu.global.u32 %0, [%1];\n"
                 : "=r"(v) : "l"(&g_flags[threadIdx.x]) : "memory");
  } while (v < target);
  __syncthreads();
}

// ---------------- prep kernels ----------------
__global__ void k_prep_w(const float* __restrict__ W1, const float* __restrict__ U1,
                         const float* __restrict__ W2, const float* __restrict__ U2) {
  int idx = blockIdx.x * blockDim.x + threadIdx.x;
  if (idx >= 4 * G4 * 512) return;
  int w   = idx >> 20;
  int rem = idx & ((1 << 20) - 1);
  int p   = rem >> 9;          // interleaved col
  int k   = rem & 511;
  int jh = p >> 2, gate = p & 3;
  int j = gate * H_ + jh;      // original column
  const float* Mt = (w==0) ? W1 : (w==1) ? U1 : (w==2) ? W2 : U2;
  float v = Mt[(size_t)k * G4 + j];
  __nv_bfloat16 hi = __float2bfloat16(v);
  __nv_bfloat16 lo = __float2bfloat16(v - __bfloat162float(hi));
  g_wsplit[w][p][k]       = hi;
  g_wsplit[w][p][512 + k] = lo;
}

__global__ void k_prep_bias(const float* __restrict__ b1, const float* __restrict__ b2) {
  int idx = blockIdx.x * blockDim.x + threadIdx.x;
  if (idx >= 2 * G4) return;
  int l = idx >> 11;
  int p = idx & (G4 - 1);
  int jh = p >> 2, gate = p & 3;
  const float* b = l ? b2 : b1;
  g_bias[l][p] = b[gate * H_ + jh];
}

__global__ void k_init() {
  int i = blockIdx.x * blockDim.x + threadIdx.x;
  if (i < 2 * B_ * KU) ((__nv_bfloat16*)g_hsplit)[i] = __float2bfloat16(0.f);
  if (i < B_ * H_)     ((float*)g_c)[i] = 0.f;
}

__global__ void k_conv(const float* __restrict__ x) {
  int i = blockIdx.x * blockDim.x + threadIdx.x;   // < M_*512
  float v = x[i];
  int m = i >> 9, k = i & 511;
  __nv_bfloat16 hi = __float2bfloat16(v);
  __nv_bfloat16 lo = __float2bfloat16(v - __bfloat162float(hi));
  g_xsplit[m][k]       = hi;
  g_xsplit[m][512 + k] = lo;
}

// ---------------- big GEMM: Zx = split(A) @ split(W)^T + bias ----------------
struct BigS {
  alignas(16) __nv_bfloat16 a_hi[2][128][72];
  alignas(16) __nv_bfloat16 a_lo[2][128][72];
  alignas(16) __nv_bfloat16 w_hi[2][128][72];
  alignas(16) __nv_bfloat16 w_lo[2][128][72];
};

__global__ void __launch_bounds__(256, 1) k_gemm_big(int widx, int lidx) {
  extern __shared__ char smraw[];
  BigS& s = *(BigS*)smraw;
  const int tid = threadIdx.x, wid = tid >> 5, lane = tid & 31;
  const int grp = lane >> 2, qid = lane & 3;
  const int mBase = blockIdx.y * 128, nBase = blockIdx.x * 128;
  const int m_off = (wid & 3) * 32, n_off = (wid >> 2) * 64;

  float acc[2][8][4];
  #pragma unroll
  for (int mt=0; mt<2; mt++)
    #pragma unroll
    for (int nt=0; nt<8; nt++)
      #pragma unroll
      for (int q=0; q<4; q++) acc[mt][nt][q] = 0.f;

  auto load_blk = [&](int kb, int bufi) {
    int k0 = kb * 64;
    #pragma unroll
    for (int i = tid; i < 1024; i += 256) {
      int r = i >> 3, ch = (i & 7) * 8;
      cpa16(&s.a_hi[bufi][r][ch], &g_xsplit[mBase + r][k0 + ch]);
      cpa16(&s.a_lo[bufi][r][ch], &g_xsplit[mBase + r][512 + k0 + ch]);
      cpa16(&s.w_hi[bufi][r][ch], &g_wsplit[widx][nBase + r][k0 + ch]);
      cpa16(&s.w_lo[bufi][r][ch], &g_wsplit[widx][nBase + r][512 + k0 + ch]);
    }
  };

  load_blk(0, 0); CP_COMMIT;
  for (int kb = 0; kb < 8; kb++) {
    CP_WAIT0; __syncthreads();
    if (kb < 7) { load_blk(kb + 1, (kb + 1) & 1); CP_COMMIT; }
    int bf = kb & 1;
    #pragma unroll
    for (int ks = 0; ks < 4; ks++) {
      const int kk = ks * 16;
      uint32_t ah[2][4], al[2][4], wh[8][2], wl[8][2];
      #pragma unroll
      for (int mt = 0; mt < 2; mt++) {
        ldA<72>(ah[mt], &s.a_hi[bf][m_off + mt*16][kk], grp, qid);
        ldA<72>(al[mt], &s.a_lo[bf][m_off + mt*16][kk], grp, qid);
      }
      #pragma unroll
      for (int nt = 0; nt < 8; nt++) {
        ldBf<72>(wh[nt], &s.w_hi[bf][n_off + nt*8][kk], grp, qid);
        ldBf<72>(wl[nt], &s.w_lo[bf][n_off + nt*8][kk], grp, qid);
      }
      #pragma unroll
      for (int nt = 0; nt < 8; nt++)
        #pragma unroll
        for (int mt = 0; mt < 2; mt++)
          MMA16816(acc[mt][nt], ah[mt], wh[nt]);
      #pragma unroll
      for (int nt = 0; nt < 8; nt++)
        #pragma unroll
        for (int mt = 0; mt < 2; mt++)
          MMA16816(acc[mt][nt], al[mt], wh[nt]);
      #pragma unroll
      for (int nt = 0; nt < 8; nt++)
        #pragma unroll
        for (int mt = 0; mt < 2; mt++)
          MMA16816(acc[mt][nt], ah[mt], wl[nt]);
    }
    __syncthreads();
  }

  #pragma unroll
  for (int mt = 0; mt < 2; mt++) {
    #pragma unroll
    for (int nt = 0; nt < 8; nt++) {
      int r = mBase + m_off + mt*16 + grp;
      int c = nBase + n_off + nt*8 + qid*2;
      float bx = g_bias[lidx][c], by = g_bias[lidx][c + 1];
      float2 v0 = make_float2(acc[mt][nt][0] + bx, acc[mt][nt][1] + by);
      *(float2*)&g_Zx[r][c] = v0;
      float2 v1 = make_float2(acc[mt][nt][2] + bx, acc[mt][nt][3] + by);
      *(float2*)&g_Zx[r + 8][c] = v1;
    }
  }
}

// ---------------- persistent recurrent pass kernel ----------------
struct StepS {
  alignas(16) __nv_bfloat16 w_hi[32][520];   // full split-K weights, resident per pass
  alignas(16) __nv_bfloat16 w_lo[32][520];
  alignas(16) __nv_bfloat16 a_hi[2][64][72];
  alignas(16) __nv_bfloat16 a_lo[2][64][72];
  alignas(16) float zs[64][36];
  alignas(16) float cst[64][8];
  unsigned base;
};

__global__ void __launch_bounds__(128, 1) k_step(int uidx, int writeX, int finalPass,
                                                 float* __restrict__ out) {
  extern __shared__ char smraw[];
  StepS& s = *(StepS*)smraw;
  const int tid = threadIdx.x, wid = tid >> 5, lane = tid & 31;
  const int grp = lane >> 2, qid = lane & 3;
  const int bx = blockIdx.x, by = blockIdx.y;
  const int nBase = bx * 32, mBase = by * 64, jhBase = bx * 8;
  const int ctaId = by * 64 + bx;
  const int m_off = (wid & 1) * 32, n_off = (wid >> 1) * 16;

  if (tid == 0) {
    unsigned bse;
    asm volatile("ld.acquire.gpu.global.u32 %0, [%1];\n"
                 : "=r"(bse) : "l"(&g_flags[ctaId]) : "memory");
    s.base = bse;
  }
  // load U slab into SMEM (once per pass): 32 rows x 1024 split-K
  for (int i = tid; i < 4096; i += 128) {
    int r = i >> 7, ch = (i & 127) * 8;
    uint4 v = *(const uint4*)&g_wsplit[uidx][nBase + r][ch];
    if (ch < 512) *(uint4*)&s.w_hi[r][ch] = v;
    else          *(uint4*)&s.w_lo[r][ch - 512] = v;
  }
  // load c state
  for (int i = tid; i < 512; i += 128)
    s.cst[i >> 3][i & 7] = g_c[mBase + (i >> 3)][jhBase + (i & 7)];
  __syncthreads();
  const unsigned base = s.base;

  const int b_l = tid >> 1, jj0 = (tid & 1) * 4;

  for (int t = 0; t < T_; t++) {
    const __nv_bfloat16 (*hsrc)[KU] = g_hsplit[t & 1];

    // Zx prefetch into registers (scoreboard hides DRAM latency behind mma loop)
    const float* zrow = &g_Zx[(mBase + b_l) * T_ + t][nBase];
    float4 zx[4];
    #pragma unroll
    for (int q = 0; q < 4; q++) zx[q] = *(const float4*)(zrow + (jj0 + q) * 4);

    float acc[2][2][4];
    #pragma unroll
    for (int mt=0; mt<2; mt++)
      #pragma unroll
      for (int nt=0; nt<2; nt++)
        #pragma unroll
        for (int q=0; q<4; q++) acc[mt][nt][q] = 0.f;

    auto load_a = [&](int kb, int bufi) {
      int k0 = kb * 64;
      #pragma unroll
      for (int i = tid; i < 512; i += 128) {
        int r = i >> 3, ch = (i & 7) * 8;
        cpa16(&s.a_hi[bufi][r][ch], &hsrc[mBase + r][k0 + ch]);
        cpa16(&s.a_lo[bufi][r][ch], &hsrc[mBase + r][512 + k0 + ch]);
      }
    };

    load_a(0, 0); CP_COMMIT;
    for (int kb = 0; kb < 8; kb++) {
      CP_WAIT0; __syncthreads();
      if (kb < 7) { load_a(kb + 1, (kb + 1) & 1); CP_COMMIT; }
      int bf = kb & 1;
      #pragma unroll
      for (int ks = 0; ks < 4; ks++) {
        const int kk = ks * 16;
        const int kw = kb * 64 + kk;
        uint32_t ah[2][4], al[2][4], wh[2][2], wl[2][2];
        #pragma unroll
        for (int mt = 0; mt < 2; mt++) {
          ldA<72>(ah[mt], &s.a_hi[bf][m_off + mt*16][kk], grp, qid);
          ldA<72>(al[mt], &s.a_lo[bf][m_off + mt*16][kk], grp, qid);
        }
        #pragma unroll
        for (int nt = 0; nt < 2; nt++) {
          ldBf<520>(wh[nt], &s.w_hi[n_off + nt*8][kw], grp, qid);
          ldBf<520>(wl[nt], &s.w_lo[n_off + nt*8][kw], grp, qid);
        }
        #pragma unroll
        for (int nt = 0; nt < 2; nt++)
          #pragma unroll
          for (int mt = 0; mt < 2; mt++)
            MMA16816(acc[mt][nt], ah[mt], wh[nt]);
        #pragma unroll
        for (int nt = 0; nt < 2; nt++)
          #pragma unroll
          for (int mt = 0; mt < 2; mt++)
            MMA16816(acc[mt][nt], al[mt], wh[nt]);
        #pragma unroll
        for (int nt = 0; nt < 2; nt++)
          #pragma unroll
          for (int mt = 0; mt < 2; mt++)
            MMA16816(acc[mt][nt], ah[mt], wl[nt]);
      }
      __syncthreads();
    }

    // accumulators -> smem
    #pragma unroll
    for (int mt = 0; mt < 2; mt++) {
      #pragma unroll
      for (int nt = 0; nt < 2; nt++) {
        int r = m_off + mt*16 + grp;
        int c = n_off + nt*8 + qid*2;
        s.zs[r][c]     = acc[mt][nt][0];
        s.zs[r][c + 1] = acc[mt][nt][1];
        s.zs[r + 8][c]     = acc[mt][nt][2];
        s.zs[r + 8][c + 1] = acc[mt][nt][3];
      }
    }
    __syncthreads();

    // gates + state update; each thread owns 4 (b_l, jh_l) cells
    __nv_bfloat16 (*hdst)[KU] = g_hsplit[(t + 1) & 1];
    #pragma unroll
    for (int q = 0; q < 4; q++) {
      int jh_l = jj0 + q;
      float zi = s.zs[b_l][jh_l*4 + 0] + zx[q].x;
      float zf = s.zs[b_l][jh_l*4 + 1] + zx[q].y;
      float zg = s.zs[b_l][jh_l*4 + 2] + zx[q].z;
      float zo = s.zs[b_l][jh_l*4 + 3] + zx[q].w;
      float ig = sigf(zi), fg = sigf(zf), gg = tanhfast(zg), og = sigf(zo);
      float c0 = s.cst[b_l][jh_l];
      float cn = fg * c0 + ig * gg;
      s.cst[b_l][jh_l] = cn;
      float h = og * tanhfast(cn);
      int bg = mBase + b_l, jg = jhBase + jh_l;
      __nv_bfloat16 hi = __float2bfloat16(h);
      __nv_bfloat16 lo = __float2bfloat16(h - __bfloat162float(hi));
      hdst[bg][jg]       = hi;
      hdst[bg][512 + jg] = lo;
      if (writeX) {
        int m = bg * T_ + t;
        g_xsplit[m][jg]       = hi;
        g_xsplit[m][512 + jg] = lo;
      }
      if (finalPass && t == T_ - 1) out[bg * H_ + jg] = h;
    }

    if (t < T_ - 1) grid_barrier(base + (unsigned)t + 1, ctaId);
  }

  // write back c state for the next pass
  __syncthreads();
  for (int i = tid; i < 512; i += 128)
    g_c[mBase + (i >> 3)][jhBase + (i & 7)] = s.cst[i >> 3][i & 7];
}

// ---------------- launch ----------------
extern "C" void kernel_launch(void* const* d_in, const int* in_sizes, int n_in,
                              void* d_out, int out_size) {
  const float* x  = (const float*)d_in[0];
  const float* W1 = (const float*)d_in[1];
  const float* U1 = (const float*)d_in[2];
  const float* b1 = (const float*)d_in[3];
  const float* W2 = (const float*)d_in[4];
  const float* U2 = (const float*)d_in[5];
  const float* b2 = (const float*)d_in[6];

  cudaFuncSetAttribute(k_gemm_big, cudaFuncAttributeMaxDynamicSharedMemorySize, (int)sizeof(BigS));
  cudaFuncSetAttribute(k_step,     cudaFuncAttributeMaxDynamicSharedMemorySize, (int)sizeof(StepS));

  k_prep_w<<<(4 * G4 * 512 + 255) / 256, 256>>>(W1, U1, W2, U2);
  k_prep_bias<<<(2 * G4 + 255) / 256, 256>>>(b1, b2);
  k_init<<<(2 * B_ * KU + 255) / 256, 256>>>();
  k_conv<<<(M_ * H_ + 255) / 256, 256>>>(x);

  for (int pass = 0; pass < 6; ++pass) {
    int widx = (pass < 5) ? 0 : 2;
    int uidx = widx + 1;
    int lidx = (pass < 5) ? 0 : 1;
    k_gemm_big<<<dim3(G4 / 128, M_ / 128), 256, sizeof(BigS)>>>(widx, lidx);
    k_step<<<dim3(64, 2), 128, sizeof(StepS)>>>(uidx, (pass < 5) ? 1 : 0,
                                                (pass == 5) ? 1 : 0, (float*)d_out);
  }
}

// round 5
// speedup vs baseline: 1.0211x; 1.0211x over previous
#include <cuda_runtime.h>
#include <cuda_bf16.h>
#include <stdint.h>

#define B_ 128
#define T_ 256
#define H_ 512
#define G4 2048          // 4*H, gate-interleaved columns p = 4*jh + gate
#define KU 1024          // unique split-K: [hi(512) | lo(512)]
#define M_ (B_*T_)       // 32768

// ---------------- device scratch (no allocs allowed) ----------------
__device__ __nv_bfloat16 g_wsplit[4][G4][KU];   // W1,U1,W2,U2: [p][ hi | lo ]
__device__ float         g_bias[2][G4];
__device__ __nv_bfloat16 g_xsplit[M_][KU];      // split activations (big-GEMM A)
__device__ float         g_Zx[M_][G4];          // x@W + b, gate-interleaved
__device__ __nv_bfloat16 g_hsplit[2][B_][KU];   // double-buffered split h
__device__ float         g_c[B_][H_];
__device__ unsigned      g_flags[2][64];        // per-group barrier flags (monotonic)

// ---------------- helpers ----------------
#define MMA16816(d, a, b) asm volatile( \
  "mma.sync.aligned.m16n8k16.row.col.f32.bf16.bf16.f32 " \
  "{%0,%1,%2,%3}, {%4,%5,%6,%7}, {%8,%9}, {%0,%1,%2,%3};\n" \
  : "+f"(d[0]), "+f"(d[1]), "+f"(d[2]), "+f"(d[3]) \
  : "r"(a[0]), "r"(a[1]), "r"(a[2]), "r"(a[3]), "r"(b[0]), "r"(b[1]))

__device__ __forceinline__ uint32_t s2u(const void* p) {
  return (uint32_t)__cvta_generic_to_shared(p);
}
__device__ __forceinline__ void ldsm4(uint32_t r[4], uint32_t addr) {
  asm volatile("ldmatrix.sync.aligned.m8n8.x4.shared.b16 {%0,%1,%2,%3}, [%4];\n"
    : "=r"(r[0]), "=r"(r[1]), "=r"(r[2]), "=r"(r[3]) : "r"(addr));
}
__device__ __forceinline__ void cpa16(void* s, const void* g) {
  uint32_t sa = s2u(s);
  asm volatile("cp.async.cg.shared.global [%0], [%1], 16;\n" :: "r"(sa), "l"(g));
}
#define CP_COMMIT asm volatile("cp.async.commit_group;\n")
#define CP_WAIT0  asm volatile("cp.async.wait_group 0;\n")

__device__ __forceinline__ float sigf(float x)     { return 1.f / (1.f + __expf(-x)); }
__device__ __forceinline__ float tanhfast(float x) { return 1.f - 2.f / (1.f + __expf(2.f*x)); }

// ---------------- prep kernels ----------------
__global__ void k_prep_w(const float* __restrict__ W1, const float* __restrict__ U1,
                         const float* __restrict__ W2, const float* __restrict__ U2) {
  int idx = blockIdx.x * blockDim.x + threadIdx.x;
  if (idx >= 4 * G4 * 512) return;
  int w   = idx >> 20;
  int rem = idx & ((1 << 20) - 1);
  int p   = rem >> 9;
  int k   = rem & 511;
  int jh = p >> 2, gate = p & 3;
  int j = gate * H_ + jh;
  const float* Mt = (w==0) ? W1 : (w==1) ? U1 : (w==2) ? W2 : U2;
  float v = Mt[(size_t)k * G4 + j];
  __nv_bfloat16 hi = __float2bfloat16(v);
  __nv_bfloat16 lo = __float2bfloat16(v - __bfloat162float(hi));
  g_wsplit[w][p][k]       = hi;
  g_wsplit[w][p][512 + k] = lo;
}

__global__ void k_prep_bias(const float* __restrict__ b1, const float* __restrict__ b2) {
  int idx = blockIdx.x * blockDim.x + threadIdx.x;
  if (idx >= 2 * G4) return;
  int l = idx >> 11;
  int p = idx & (G4 - 1);
  int jh = p >> 2, gate = p & 3;
  const float* b = l ? b2 : b1;
  g_bias[l][p] = b[gate * H_ + jh];
}

__global__ void k_init() {
  int i = blockIdx.x * blockDim.x + threadIdx.x;
  if (i < 2 * B_ * KU) ((__nv_bfloat16*)g_hsplit)[i] = __float2bfloat16(0.f);
  if (i < B_ * H_)     ((float*)g_c)[i] = 0.f;
}

__global__ void k_conv(const float* __restrict__ x) {
  int i = blockIdx.x * blockDim.x + threadIdx.x;
  float v = x[i];
  int m = i >> 9, k = i & 511;
  __nv_bfloat16 hi = __float2bfloat16(v);
  __nv_bfloat16 lo = __float2bfloat16(v - __bfloat162float(hi));
  g_xsplit[m][k]       = hi;
  g_xsplit[m][512 + k] = lo;
}

// ---------------- big GEMM: Zx = split(A) @ split(W)^T + bias ----------------
struct BigS {
  alignas(16) __nv_bfloat16 a_hi[2][128][72];
  alignas(16) __nv_bfloat16 a_lo[2][128][72];
  alignas(16) __nv_bfloat16 w_hi[2][128][72];
  alignas(16) __nv_bfloat16 w_lo[2][128][72];
};

__global__ void __launch_bounds__(256, 1) k_gemm_big(int widx, int lidx) {
  extern __shared__ char smraw[];
  BigS& s = *(BigS*)smraw;
  const int tid = threadIdx.x, wid = tid >> 5, lane = tid & 31;
  const int grp = lane >> 2, qid = lane & 3;
  const int mBase = blockIdx.y * 128, nBase = blockIdx.x * 128;
  const int m_off = (wid & 3) * 32, n_off = (wid >> 2) * 64;
  // ldmatrix lane offsets
  const int aR = lane & 15,                  aC = (lane >> 4) << 3;
  const int bR = ((lane>>4)<<3) + (lane&7),  bC = ((lane >> 3) & 1) << 3;

  float acc[2][8][4];
  #pragma unroll
  for (int mt=0; mt<2; mt++)
    #pragma unroll
    for (int nt=0; nt<8; nt++)
      #pragma unroll
      for (int q=0; q<4; q++) acc[mt][nt][q] = 0.f;

  auto load_blk = [&](int kb, int bufi) {
    int k0 = kb * 64;
    #pragma unroll
    for (int i = tid; i < 1024; i += 256) {
      int r = i >> 3, ch = (i & 7) * 8;
      cpa16(&s.a_hi[bufi][r][ch], &g_xsplit[mBase + r][k0 + ch]);
      cpa16(&s.a_lo[bufi][r][ch], &g_xsplit[mBase + r][512 + k0 + ch]);
      cpa16(&s.w_hi[bufi][r][ch], &g_wsplit[widx][nBase + r][k0 + ch]);
      cpa16(&s.w_lo[bufi][r][ch], &g_wsplit[widx][nBase + r][512 + k0 + ch]);
    }
  };

  uint32_t saH[2], saL[2], swH[2], swL[2];
  #pragma unroll
  for (int b = 0; b < 2; b++) {
    saH[b] = s2u(&s.a_hi[b][0][0]); saL[b] = s2u(&s.a_lo[b][0][0]);
    swH[b] = s2u(&s.w_hi[b][0][0]); swL[b] = s2u(&s.w_lo[b][0][0]);
  }

  load_blk(0, 0); CP_COMMIT;
  for (int kb = 0; kb < 8; kb++) {
    CP_WAIT0; __syncthreads();
    if (kb < 7) { load_blk(kb + 1, (kb + 1) & 1); CP_COMMIT; }
    int bf = kb & 1;
    #pragma unroll
    for (int ks = 0; ks < 4; ks++) {
      const int kk = ks * 16;
      uint32_t ah[2][4], al[2][4], wh[4][4], wl[4][4];
      #pragma unroll
      for (int mt = 0; mt < 2; mt++) {
        uint32_t off = (uint32_t)(((m_off + mt*16 + aR) * 72 + kk + aC) * 2);
        ldsm4(ah[mt], saH[bf] + off);
        ldsm4(al[mt], saL[bf] + off);
      }
      #pragma unroll
      for (int np = 0; np < 4; np++) {
        uint32_t off = (uint32_t)(((n_off + np*16 + bR) * 72 + kk + bC) * 2);
        ldsm4(wh[np], swH[bf] + off);
        ldsm4(wl[np], swL[bf] + off);
      }
      #pragma unroll
      for (int np = 0; np < 4; np++)
        #pragma unroll
        for (int hf = 0; hf < 2; hf++)
          #pragma unroll
          for (int mt = 0; mt < 2; mt++)
            MMA16816(acc[mt][np*2+hf], ah[mt], (&wh[np][hf*2]));
      #pragma unroll
      for (int np = 0; np < 4; np++)
        #pragma unroll
        for (int hf = 0; hf < 2; hf++)
          #pragma unroll
          for (int mt = 0; mt < 2; mt++)
            MMA16816(acc[mt][np*2+hf], al[mt], (&wh[np][hf*2]));
      #pragma unroll
      for (int np = 0; np < 4; np++)
        #pragma unroll
        for (int hf = 0; hf < 2; hf++)
          #pragma unroll
          for (int mt = 0; mt < 2; mt++)
            MMA16816(acc[mt][np*2+hf], ah[mt], (&wl[np][hf*2]));
    }
    __syncthreads();
  }

  #pragma unroll
  for (int mt = 0; mt < 2; mt++) {
    #pragma unroll
    for (int nt = 0; nt < 8; nt++) {
      int r = mBase + m_off + mt*16 + grp;
      int c = nBase + n_off + nt*8 + qid*2;
      float bx = g_bias[lidx][c], by = g_bias[lidx][c + 1];
      float2 v0 = make_float2(acc[mt][nt][0] + bx, acc[mt][nt][1] + by);
      *(float2*)&g_Zx[r][c] = v0;
      float2 v1 = make_float2(acc[mt][nt][2] + bx, acc[mt][nt][3] + by);
      *(float2*)&g_Zx[r + 8][c] = v1;
    }
  }
}

// ---------------- persistent recurrent pass kernel ----------------
struct StepS {
  alignas(16) __nv_bfloat16 w_hi[32][520];   // U slab, resident per pass
  alignas(16) __nv_bfloat16 w_lo[32][520];
  alignas(16) __nv_bfloat16 a_hi[2][64][136];
  alignas(16) __nv_bfloat16 a_lo[2][64][136];
  alignas(16) float zs[64][36];
  alignas(16) float cst[64][8];
  unsigned base;
};

__global__ void __launch_bounds__(256, 1) k_step(int uidx, int writeX, int finalPass,
                                                 float* __restrict__ out) {
  extern __shared__ char smraw[];
  StepS& s = *(StepS*)smraw;
  const int tid = threadIdx.x, wid = tid >> 5, lane = tid & 31;
  const int grp = lane >> 2, qid = lane & 3;
  const int bx = blockIdx.x, by = blockIdx.y;
  const int nBase = bx * 32, mBase = by * 64, jhBase = bx * 8;
  const int m_off = (wid & 3) * 16, n_off = (wid >> 2) * 16;
  const int aR = lane & 15,                  aC = (lane >> 4) << 3;
  const int bR = ((lane>>4)<<3) + (lane&7),  bC = ((lane >> 3) & 1) << 3;

  if (tid == 0) {
    unsigned b;
    asm volatile("ld.acquire.gpu.global.u32 %0, [%1];\n"
                 : "=r"(b) : "l"(&g_flags[by][bx]) : "memory");
    s.base = b;
  }
  // load U slab (once per pass): 32 rows x 1024 split-K
  for (int i = tid; i < 4096; i += 256) {
    int r = i >> 7, ch = (i & 127) * 8;
    uint4 v = *(const uint4*)&g_wsplit[uidx][nBase + r][ch];
    if (ch < 512) *(uint4*)&s.w_hi[r][ch] = v;
    else          *(uint4*)&s.w_lo[r][ch - 512] = v;
  }
  for (int i = tid; i < 512; i += 256)
    s.cst[i >> 3][i & 7] = g_c[mBase + (i >> 3)][jhBase + (i & 7)];
  __syncthreads();
  const unsigned base = s.base;

  uint32_t saH[2], saL[2];
  saH[0] = s2u(&s.a_hi[0][0][0]); saH[1] = s2u(&s.a_hi[1][0][0]);
  saL[0] = s2u(&s.a_lo[0][0][0]); saL[1] = s2u(&s.a_lo[1][0][0]);
  const uint32_t swH = s2u(&s.w_hi[0][0]), swL = s2u(&s.w_lo[0][0]);
  const uint32_t aOff = (uint32_t)(((m_off + aR) * 136 + aC) * 2);
  const uint32_t wOff = (uint32_t)(((n_off + bR) * 520 + bC) * 2);

  const int b_l = tid >> 2, jh0 = (tid & 3) * 2;   // 2 cells per thread

  for (int t = 0; t < T_; t++) {
    const __nv_bfloat16 (*hsrc)[KU] = g_hsplit[t & 1];

    // Zx prefetch (long-scoreboard hidden behind mma loop)
    const float* zrow = &g_Zx[(mBase + b_l) * T_ + t][nBase + jh0 * 4];
    float4 zx0 = *(const float4*)zrow;
    float4 zx1 = *(const float4*)(zrow + 4);

    float acc[2][4];
    #pragma unroll
    for (int nt=0; nt<2; nt++)
      #pragma unroll
      for (int q=0; q<4; q++) acc[nt][q] = 0.f;

    auto load_a = [&](int kb, int bufi) {
      int k0 = kb * 128;
      #pragma unroll
      for (int i = tid; i < 1024; i += 256) {
        int r = i >> 4, ch = (i & 15) * 8;
        cpa16(&s.a_hi[bufi][r][ch], &hsrc[mBase + r][k0 + ch]);
        cpa16(&s.a_lo[bufi][r][ch], &hsrc[mBase + r][512 + k0 + ch]);
      }
    };

    load_a(0, 0); CP_COMMIT;
    #pragma unroll
    for (int kb = 0; kb < 4; kb++) {
      CP_WAIT0; __syncthreads();
      if (kb < 3) { load_a(kb + 1, (kb + 1) & 1); CP_COMMIT; }
      int bf = kb & 1;
      #pragma unroll
      for (int ks = 0; ks < 8; ks++) {
        const int kk = ks * 16;
        const int kw = kb * 128 + kk;
        uint32_t ah[4], al[4], wh[4], wl[4];
        ldsm4(ah, saH[bf] + aOff + kk * 2);
        ldsm4(al, saL[bf] + aOff + kk * 2);
        ldsm4(wh, swH + wOff + kw * 2);
        ldsm4(wl, swL + wOff + kw * 2);
        #pragma unroll
        for (int hf = 0; hf < 2; hf++) MMA16816(acc[hf], ah, (&wh[hf*2]));
        #pragma unroll
        for (int hf = 0; hf < 2; hf++) MMA16816(acc[hf], al, (&wh[hf*2]));
        #pragma unroll
        for (int hf = 0; hf < 2; hf++) MMA16816(acc[hf], ah, (&wl[hf*2]));
      }
      __syncthreads();
    }

    // accumulators -> smem
    #pragma unroll
    for (int nt = 0; nt < 2; nt++) {
      int c = n_off + nt*8 + qid*2;
      s.zs[m_off + grp][c]         = acc[nt][0];
      s.zs[m_off + grp][c + 1]     = acc[nt][1];
      s.zs[m_off + 8 + grp][c]     = acc[nt][2];
      s.zs[m_off + 8 + grp][c + 1] = acc[nt][3];
    }
    __syncthreads();

    // gates + state update: 2 cells per thread (b_l, jh0), (b_l, jh0+1)
    __nv_bfloat16 (*hdst)[KU] = g_hsplit[(t + 1) & 1];
    float hv[2];
    #pragma unroll
    for (int q = 0; q < 2; q++) {
      int jh = jh0 + q;
      float4 z4 = q ? zx1 : zx0;
      float zi = s.zs[b_l][jh*4 + 0] + z4.x;
      float zf = s.zs[b_l][jh*4 + 1] + z4.y;
      float zg = s.zs[b_l][jh*4 + 2] + z4.z;
      float zo = s.zs[b_l][jh*4 + 3] + z4.w;
      float ig = sigf(zi), fg = sigf(zf), gg = tanhfast(zg), og = sigf(zo);
      float c0 = s.cst[b_l][jh];
      float cn = fg * c0 + ig * gg;
      s.cst[b_l][jh] = cn;
      hv[q] = og * tanhfast(cn);
    }
    {
      int bg = mBase + b_l, jg = jhBase + jh0;
      __nv_bfloat16 h0 = __float2bfloat16(hv[0]);
      __nv_bfloat16 h1 = __float2bfloat16(hv[1]);
      __nv_bfloat162 phi; phi.x = h0; phi.y = h1;
      __nv_bfloat162 plo;
      plo.x = __float2bfloat16(hv[0] - __bfloat162float(h0));
      plo.y = __float2bfloat16(hv[1] - __bfloat162float(h1));
      *(__nv_bfloat162*)&hdst[bg][jg]       = phi;
      *(__nv_bfloat162*)&hdst[bg][512 + jg] = plo;
      if (writeX) {
        int m = bg * T_ + t;
        *(__nv_bfloat162*)&g_xsplit[m][jg]       = phi;
        *(__nv_bfloat162*)&g_xsplit[m][512 + jg] = plo;
      }
      if (finalPass && t == T_ - 1) {
        out[bg * H_ + jg]     = hv[0];
        out[bg * H_ + jg + 1] = hv[1];
      }
    }

    if (t < T_ - 1) {
      // group barrier (64 CTAs sharing this by)
      __threadfence();
      __syncthreads();
      unsigned target = base + (unsigned)t + 1;
      if (tid == 0)
        asm volatile("st.release.gpu.global.u32 [%0], %1;\n"
                     :: "l"(&g_flags[by][bx]), "r"(target) : "memory");
      if (tid < 64) {
        unsigned v;
        do {
          asm volatile("ld.acquire.gpu.global.u32 %0, [%1];\n"
                       : "=r"(v) : "l"(&g_flags[by][tid]) : "memory");
        } while (v < target);
      }
      __syncthreads();
    }
  }

  __syncthreads();
  for (int i = tid; i < 512; i += 256)
    g_c[mBase + (i >> 3)][jhBase + (i & 7)] = s.cst[i >> 3][i & 7];
}

// ---------------- launch ----------------
extern "C" void kernel_launch(void* const* d_in, const int* in_sizes, int n_in,
                              void* d_out, int out_size) {
  const float* x  = (const float*)d_in[0];
  const float* W1 = (const float*)d_in[1];
  const float* U1 = (const float*)d_in[2];
  const float* b1 = (const float*)d_in[3];
  const float* W2 = (const float*)d_in[4];
  const float* U2 = (const float*)d_in[5];
  const float* b2 = (const float*)d_in[6];

  cudaFuncSetAttribute(k_gemm_big, cudaFuncAttributeMaxDynamicSharedMemorySize, (int)sizeof(BigS));
  cudaFuncSetAttribute(k_step,     cudaFuncAttributeMaxDynamicSharedMemorySize, (int)sizeof(StepS));

  k_prep_w<<<(4 * G4 * 512 + 255) / 256, 256>>>(W1, U1, W2, U2);
  k_prep_bias<<<(2 * G4 + 255) / 256, 256>>>(b1, b2);
  k_init<<<(2 * B_ * KU + 255) / 256, 256>>>();
  k_conv<<<(M_ * H_ + 255) / 256, 256>>>(x);

  for (int pass = 0; pass < 6; ++pass) {
    int widx = (pass < 5) ? 0 : 2;
    int uidx = widx + 1;
    int lidx = (pass < 5) ? 0 : 1;
    k_gemm_big<<<dim3(G4 / 128, M_ / 128), 256, sizeof(BigS)>>>(widx, lidx);
    k_step<<<dim3(64, 2), 256, sizeof(StepS)>>>(uidx, (pass < 5) ? 1 : 0,
                                                (pass == 5) ? 1 : 0, (float*)d_out);
  }
}

// round 9
// speedup vs baseline: 1.1986x; 1.1738x over previous
#include <cuda_runtime.h>
#include <cuda_fp16.h>
#include <stdint.h>

#define B_ 128
#define T_ 256
#define H_ 512
#define G4 2048          // 4*H, gate-interleaved columns p = 4*jh + gate
#define KW 1024          // weight split-K: [hi(512) | lo(512)]
#define M_ (B_*T_)       // 32768

// ---------------- device scratch (no allocs allowed) ----------------
__device__ __half g_wsplit[4][G4][KW];    // W1,U1,W2,U2: [p][ hi | lo ], fp16
__device__ float  g_bias[2][G4];
__device__ __half g_x[M_][H_];            // single-fp16 activations (big-GEMM A)
__device__ float  g_Zx[M_][G4];           // x@W + b, gate-interleaved
__device__ __half g_hbuf[2][B_][H_];      // double-buffered fp16 h
__device__ float  g_c[B_][H_];
__device__ unsigned g_flags[2][64];       // per-group barrier flags (monotonic)

// ---------------- helpers ----------------
#define MMA16816(d, a, b) asm volatile( \
  "mma.sync.aligned.m16n8k16.row.col.f32.f16.f16.f32 " \
  "{%0,%1,%2,%3}, {%4,%5,%6,%7}, {%8,%9}, {%0,%1,%2,%3};\n" \
  : "+f"(d[0]), "+f"(d[1]), "+f"(d[2]), "+f"(d[3]) \
  : "r"(a[0]), "r"(a[1]), "r"(a[2]), "r"(a[3]), "r"(b[0]), "r"(b[1]))

__device__ __forceinline__ uint32_t s2u(const void* p) {
  return (uint32_t)__cvta_generic_to_shared(p);
}
__device__ __forceinline__ void ldsm4(uint32_t r[4], uint32_t addr) {
  asm volatile("ldmatrix.sync.aligned.m8n8.x4.shared.b16 {%0,%1,%2,%3}, [%4];\n"
    : "=r"(r[0]), "=r"(r[1]), "=r"(r[2]), "=r"(r[3]) : "r"(addr));
}
__device__ __forceinline__ void cpa16(void* s, const void* g) {
  uint32_t sa = s2u(s);
  asm volatile("cp.async.cg.shared.global [%0], [%1], 16;\n" :: "r"(sa), "l"(g));
}
#define CP_COMMIT asm volatile("cp.async.commit_group;\n")
#define CP_WAIT0  asm volatile("cp.async.wait_group 0;\n")

__device__ __forceinline__ float sigf(float x)     { return 1.f / (1.f + __expf(-x)); }
__device__ __forceinline__ float tanhfast(float x) { return 1.f - 2.f / (1.f + __expf(2.f*x)); }

// ---------------- prep (fused, launch #1) ----------------
__global__ void k_prep(const float* __restrict__ W1, const float* __restrict__ U1,
                       const float* __restrict__ W2, const float* __restrict__ U2,
                       const float* __restrict__ b1, const float* __restrict__ b2) {
  int idx = blockIdx.x * blockDim.x + threadIdx.x;
  if (idx < 4 * G4 * 512) {
    int w   = idx >> 20;
    int rem = idx & ((1 << 20) - 1);
    int p   = rem >> 9;
    int k   = rem & 511;
    int jh = p >> 2, gate = p & 3;
    int j = gate * H_ + jh;
    const float* Mt = (w==0) ? W1 : (w==1) ? U1 : (w==2) ? W2 : U2;
    float v = Mt[(size_t)k * G4 + j];
    __half hi = __float2half(v);
    __half lo = __float2half(v - __half2float(hi));
    g_wsplit[w][p][k]       = hi;
    g_wsplit[w][p][512 + k] = lo;
  }
  if (idx < 2 * G4) {
    int l = idx >> 11;
    int p = idx & (G4 - 1);
    int jh = p >> 2, gate = p & 3;
    const float* b = l ? b2 : b1;
    g_bias[l][p] = b[gate * H_ + jh];
  }
  if (idx < 2 * B_ * H_) ((__half*)g_hbuf)[idx] = __float2half(0.f);
  if (idx < B_ * H_)     ((float*)g_c)[idx] = 0.f;
}

// ---------------- conv (launch #2): x fp32 -> single fp16 ----------------
__global__ void k_conv(const float* __restrict__ x) {
  int i = blockIdx.x * blockDim.x + threadIdx.x;
  ((__half*)g_x)[i] = __float2half(x[i]);
}

// ---------------- big GEMM: Zx = A(fp16) @ [Whi|Wlo]^T + bias ----------------
struct BigS {
  alignas(16) __half a[2][128][72];
  alignas(16) __half w_hi[2][128][72];
  alignas(16) __half w_lo[2][128][72];
};

__global__ void __launch_bounds__(256, 1) k_gemm_big(int widx, int lidx) {
  extern __shared__ char smraw[];
  BigS& s = *(BigS*)smraw;
  const int tid = threadIdx.x, wid = tid >> 5, lane = tid & 31;
  const int grp = lane >> 2, qid = lane & 3;
  const int mBase = blockIdx.y * 128, nBase = blockIdx.x * 128;
  const int m_off = (wid & 3) * 32, n_off = (wid >> 2) * 64;
  const int aR = lane & 15,                  aC = (lane >> 4) << 3;
  const int bR = ((lane>>4)<<3) + (lane&7),  bC = ((lane >> 3) & 1) << 3;

  float acc[2][8][4];
  #pragma unroll
  for (int mt=0; mt<2; mt++)
    #pragma unroll
    for (int nt=0; nt<8; nt++)
      #pragma unroll
      for (int q=0; q<4; q++) acc[mt][nt][q] = 0.f;

  auto load_blk = [&](int kb, int bufi) {
    int k0 = kb * 64;
    #pragma unroll
    for (int i = tid; i < 1024; i += 256) {       // A: 128 x 64 fp16
      int r = i >> 3, ch = (i & 7) * 8;
      cpa16(&s.a[bufi][r][ch], &g_x[mBase + r][k0 + ch]);
    }
    #pragma unroll
    for (int i = tid; i < 2048; i += 256) {       // W hi + lo: 128 x 64 each
      int j = i & 1023;
      int r = j >> 3, ch = (j & 7) * 8;
      if (i < 1024) cpa16(&s.w_hi[bufi][r][ch], &g_wsplit[widx][nBase + r][k0 + ch]);
      else          cpa16(&s.w_lo[bufi][r][ch], &g_wsplit[widx][nBase + r][512 + k0 + ch]);
    }
  };

  uint32_t sa[2], swH[2], swL[2];
  #pragma unroll
  for (int b = 0; b < 2; b++) {
    sa[b]  = s2u(&s.a[b][0][0]);
    swH[b] = s2u(&s.w_hi[b][0][0]);
    swL[b] = s2u(&s.w_lo[b][0][0]);
  }

  load_blk(0, 0); CP_COMMIT;
  for (int kb = 0; kb < 8; kb++) {
    CP_WAIT0; __syncthreads();
    if (kb < 7) { load_blk(kb + 1, (kb + 1) & 1); CP_COMMIT; }
    int bf = kb & 1;
    #pragma unroll
    for (int ks = 0; ks < 4; ks++) {
      const int kk = ks * 16;
      uint32_t af[2][4], wh[4][4], wl[4][4];
      #pragma unroll
      for (int mt = 0; mt < 2; mt++) {
        uint32_t off = (uint32_t)(((m_off + mt*16 + aR) * 72 + kk + aC) * 2);
        ldsm4(af[mt], sa[bf] + off);
      }
      #pragma unroll
      for (int np = 0; np < 4; np++) {
        uint32_t off = (uint32_t)(((n_off + np*16 + bR) * 72 + kk + bC) * 2);
        ldsm4(wh[np], swH[bf] + off);
        ldsm4(wl[np], swL[bf] + off);
      }
      #pragma unroll
      for (int np = 0; np < 4; np++)
        #pragma unroll
        for (int hf = 0; hf < 2; hf++)
          #pragma unroll
          for (int mt = 0; mt < 2; mt++)
            MMA16816(acc[mt][np*2+hf], af[mt], (&wh[np][hf*2]));
      #pragma unroll
      for (int np = 0; np < 4; np++)
        #pragma unroll
        for (int hf = 0; hf < 2; hf++)
          #pragma unroll
          for (int mt = 0; mt < 2; mt++)
            MMA16816(acc[mt][np*2+hf], af[mt], (&wl[np][hf*2]));
    }
    __syncthreads();
  }

  #pragma unroll
  for (int mt = 0; mt < 2; mt++) {
    #pragma unroll
    for (int nt = 0; nt < 8; nt++) {
      int r = mBase + m_off + mt*16 + grp;
      int c = nBase + n_off + nt*8 + qid*2;
      float bx = g_bias[lidx][c], by = g_bias[lidx][c + 1];
      float2 v0 = make_float2(acc[mt][nt][0] + bx, acc[mt][nt][1] + by);
      *(float2*)&g_Zx[r][c] = v0;
      float2 v1 = make_float2(acc[mt][nt][2] + bx, acc[mt][nt][3] + by);
      *(float2*)&g_Zx[r + 8][c] = v1;
    }
  }
}

// ---------------- persistent recurrent pass kernel ----------------
struct StepS {
  alignas(16) __half w_hi[32][520];     // U hi slab, resident per pass
  alignas(16) __half w_lo[32][520];     // U lo slab
  alignas(16) __half a[2][64][136];     // fp16 h tile, double buffered
  alignas(16) float zs[64][36];
  alignas(16) float cst[64][8];
  unsigned base;
};

__global__ void __launch_bounds__(256, 1) k_step(int uidx, int writeX, int finalPass,
                                                 float* __restrict__ out) {
  extern __shared__ char smraw[];
  StepS& s = *(StepS*)smraw;
  const int tid = threadIdx.x, wid = tid >> 5, lane = tid & 31;
  const int grp = lane >> 2, qid = lane & 3;
  const int bx = blockIdx.x, by = blockIdx.y;
  const int nBase = bx * 32, mBase = by * 64, jhBase = bx * 8;
  const int m_off = (wid & 3) * 16, n_off = (wid >> 2) * 16;
  const int aR = lane & 15,                  aC = (lane >> 4) << 3;
  const int bR = ((lane>>4)<<3) + (lane&7),  bC = ((lane >> 3) & 1) << 3;

  if (tid == 0) {
    unsigned b;
    asm volatile("ld.acquire.gpu.global.u32 %0, [%1];\n"
                 : "=r"(b) : "l"(&g_flags[by][bx]) : "memory");
    s.base = b;
  }
  // load U slab (once per pass): 32 rows x 1024 (hi|lo)
  for (int i = tid; i < 4096; i += 256) {
    int r = i >> 7, ch = (i & 127) * 8;
    uint4 v = *(const uint4*)&g_wsplit[uidx][nBase + r][ch];
    if (ch < 512) *(uint4*)&s.w_hi[r][ch] = v;
    else          *(uint4*)&s.w_lo[r][ch - 512] = v;
  }
  for (int i = tid; i < 512; i += 256)
    s.cst[i >> 3][i & 7] = g_c[mBase + (i >> 3)][jhBase + (i & 7)];
  __syncthreads();
  const unsigned base = s.base;

  uint32_t sa[2];
  sa[0] = s2u(&s.a[0][0][0]); sa[1] = s2u(&s.a[1][0][0]);
  const uint32_t swH = s2u(&s.w_hi[0][0]), swL = s2u(&s.w_lo[0][0]);
  const uint32_t aOff = (uint32_t)(((m_off + aR) * 136 + aC) * 2);
  const uint32_t wOff = (uint32_t)(((n_off + bR) * 520 + bC) * 2);

  const int b_l = tid >> 2, jh0 = (tid & 3) * 2;   // 2 cells per thread

  for (int t = 0; t < T_; t++) {
    const __half (*hsrc)[H_] = g_hbuf[t & 1];

    // Zx prefetch (long-scoreboard hidden behind mma loop)
    const float* zrow = &g_Zx[(mBase + b_l) * T_ + t][nBase + jh0 * 4];
    float4 zx0 = *(const float4*)zrow;
    float4 zx1 = *(const float4*)(zrow + 4);

    float acc[2][4];
    #pragma unroll
    for (int nt=0; nt<2; nt++)
      #pragma unroll
      for (int q=0; q<4; q++) acc[nt][q] = 0.f;

    auto load_a = [&](int kb, int bufi) {
      int k0 = kb * 128;
      #pragma unroll
      for (int i = tid; i < 1024; i += 256) {
        int r = i >> 4, ch = (i & 15) * 8;
        cpa16(&s.a[bufi][r][ch], &hsrc[mBase + r][k0 + ch]);
      }
    };

    load_a(0, 0); CP_COMMIT;
    #pragma unroll
    for (int kb = 0; kb < 4; kb++) {
      CP_WAIT0; __syncthreads();
      if (kb < 3) { load_a(kb + 1, (kb + 1) & 1); CP_COMMIT; }
      int bf = kb & 1;
      #pragma unroll
      for (int ks = 0; ks < 8; ks++) {
        const int kk = ks * 16;
        const int kw = kb * 128 + kk;
        uint32_t af[4], wh[4], wl[4];
        ldsm4(af, sa[bf] + aOff + kk * 2);
        ldsm4(wh, swH + wOff + kw * 2);
        ldsm4(wl, swL + wOff + kw * 2);
        #pragma unroll
        for (int hf = 0; hf < 2; hf++) MMA16816(acc[hf], af, (&wh[hf*2]));
        #pragma unroll
        for (int hf = 0; hf < 2; hf++) MMA16816(acc[hf], af, (&wl[hf*2]));
      }
      __syncthreads();
    }

    // accumulators -> smem
    #pragma unroll
    for (int nt = 0; nt < 2; nt++) {
      int c = n_off + nt*8 + qid*2;
      s.zs[m_off + grp][c]         = acc[nt][0];
      s.zs[m_off + grp][c + 1]     = acc[nt][1];
      s.zs[m_off + 8 + grp][c]     = acc[nt][2];
      s.zs[m_off + 8 + grp][c + 1] = acc[nt][3];
    }
    __syncthreads();

    // gates + state update: 2 cells per thread
    __half (*hdst)[H_] = g_hbuf[(t + 1) & 1];
    float hv[2];
    #pragma unroll
    for (int q = 0; q < 2; q++) {
      int jh = jh0 + q;
      float4 z4 = q ? zx1 : zx0;
      float zi = s.zs[b_l][jh*4 + 0] + z4.x;
      float zf = s.zs[b_l][jh*4 + 1] + z4.y;
      float zg = s.zs[b_l][jh*4 + 2] + z4.z;
      float zo = s.zs[b_l][jh*4 + 3] + z4.w;
      float ig = sigf(zi), fg = sigf(zf), gg = tanhfast(zg), og = sigf(zo);
      float c0 = s.cst[b_l][jh];
      float cn = fg * c0 + ig * gg;
      s.cst[b_l][jh] = cn;
      hv[q] = og * tanhfast(cn);
    }
    {
      int bg = mBase + b_l, jg = jhBase + jh0;
      __half2 ph;
      ph.x = __float2half(hv[0]);
      ph.y = __float2half(hv[1]);
      *(__half2*)&hdst[bg][jg] = ph;
      if (writeX) {
        int m = bg * T_ + t;
        *(__half2*)&g_x[m][jg] = ph;
      }
      if (finalPass && t == T_ - 1) {
        out[bg * H_ + jg]     = hv[0];
        out[bg * H_ + jg + 1] = hv[1];
      }
    }

    if (t < T_ - 1) {
      // group barrier (64 CTAs sharing this by)
      __threadfence();
      __syncthreads();
      unsigned target = base + (unsigned)t + 1;
      if (tid == 0)
        asm volatile("st.release.gpu.global.u32 [%0], %1;\n"
                     :: "l"(&g_flags[by][bx]), "r"(target) : "memory");
      if (tid < 64) {
        unsigned v;
        do {
          asm volatile("ld.acquire.gpu.global.u32 %0, [%1];\n"
                       : "=r"(v) : "l"(&g_flags[by][tid]) : "memory");
        } while (v < target);
      }
      __syncthreads();
    }
  }

  __syncthreads();
  for (int i = tid; i < 512; i += 256)
    g_c[mBase + (i >> 3)][jhBase + (i & 7)] = s.cst[i >> 3][i & 7];
}

// ---------------- launch ----------------
extern "C" void kernel_launch(void* const* d_in, const int* in_sizes, int n_in,
                              void* d_out, int out_size) {
  const float* x  = (const float*)d_in[0];
  const float* W1 = (const float*)d_in[1];
  const float* U1 = (const float*)d_in[2];
  const float* b1 = (const float*)d_in[3];
  const float* W2 = (const float*)d_in[4];
  const float* U2 = (const float*)d_in[5];
  const float* b2 = (const float*)d_in[6];

  cudaFuncSetAttribute(k_gemm_big, cudaFuncAttributeMaxDynamicSharedMemorySize, (int)sizeof(BigS));
  cudaFuncSetAttribute(k_step,     cudaFuncAttributeMaxDynamicSharedMemorySize, (int)sizeof(StepS));

  k_prep<<<(4 * G4 * 512 + 255) / 256, 256>>>(W1, U1, W2, U2, b1, b2);
  k_conv<<<(M_ * H_ + 255) / 256, 256>>>(x);

  for (int pass = 0; pass < 6; ++pass) {
    int widx = (pass < 5) ? 0 : 2;
    int uidx = widx + 1;
    int lidx = (pass < 5) ? 0 : 1;
    k_gemm_big<<<dim3(G4 / 128, M_ / 128), 256, sizeof(BigS)>>>(widx, lidx);
    k_step<<<dim3(64, 2), 256, sizeof(StepS)>>>(uidx, (pass < 5) ? 1 : 0,
                                                (pass == 5) ? 1 : 0, (float*)d_out);
  }
}